// round 3
// baseline (speedup 1.0000x reference)
#include <cuda_runtime.h>
#include <math.h>

#define BB   32
#define SS   256
#define CC   1024
#define DW   768
#define HH   256
#define G4   1024          // 4*H
#define NTAG 9
#define WIH_STRIDE 2816

// ---------------- scratch (static device globals; no allocations) ----------------
__device__ float g_v[BB*SS];                 // [b][s] broadcast scalar
__device__ float g_wsum[2*G4];               // [dir][gate] rowsum of Wih[:,768:]
__device__ float g_bias[2*G4];               // bih+bhh
__device__ float g_pre[2*SS*G4*BB];          // [dir][t][g][b]  (64 MB)
__device__ float g_hbuf[2*2*HH*BB];          // [dir][parity][j][b]
__device__ float g_hs[2*SS*BB*HH];           // [dir][t][b][j]  (16 MB)
__device__ float g_loss_sum;
__device__ float g_loss_cnt;
__device__ unsigned g_barcnt;
__device__ unsigned g_bargen;

// ---------------- helpers ----------------
__device__ __forceinline__ float sigmoidf_(float x) { return 1.f / (1.f + __expf(-x)); }

__device__ __forceinline__ void gridbar(unsigned nb) {
    __syncthreads();
    if (threadIdx.x == 0) {
        __threadfence();
        unsigned gen = *(volatile unsigned*)&g_bargen;
        if (atomicAdd(&g_barcnt, 1u) == nb - 1u) {
            *(volatile unsigned*)&g_barcnt = 0u;
            __threadfence();
            atomicAdd(&g_bargen, 1u);
        } else {
            while (*(volatile unsigned*)&g_bargen == gen) { }
            __threadfence();
        }
    }
    __syncthreads();
}

// ---------------- kernel 1: segment-mean scalar v[b,s] ----------------
// one warp per token; 8 warps per block
__global__ void __launch_bounds__(256) prep_v_kernel(const float* __restrict__ char_embs,
                                                     const int*   __restrict__ spans) {
    int tid  = threadIdx.x;
    int lane = tid & 31;
    int token = blockIdx.x * 8 + (tid >> 5);
    int st = spans[token * 2 + 0];
    int en = spans[token * 2 + 1];
    float s = 0.f;
    if (st >= 0) {
        int b = token >> 8;
        for (int c = st; c <= en; ++c) {
            const float* p = char_embs + ((size_t)(b * CC + c)) * DW;
            float acc = 0.f;
            for (int d = lane; d < DW; d += 32) acc += p[d];
            s += acc;
        }
        #pragma unroll
        for (int off = 16; off; off >>= 1) s += __shfl_xor_sync(0xffffffffu, s, off);
        s /= (768.f * (float)(en - st + 1));
    }
    if (lane == 0) g_v[token] = (st >= 0) ? s : 0.f;
}

// ---------------- kernel 2: wsum + bias + zero loss accumulators ----------------
// one warp per gate-row (2048 rows)
__global__ void __launch_bounds__(256) prep_w_kernel(
        const float* __restrict__ WihF, const float* __restrict__ WihB,
        const float* __restrict__ bihF, const float* __restrict__ bhhF,
        const float* __restrict__ bihB, const float* __restrict__ bhhB) {
    int tid  = threadIdx.x;
    int lane = tid & 31;
    int row  = blockIdx.x * 8 + (tid >> 5);     // 0..2047
    int dir  = row >> 10;
    int g    = row & 1023;
    const float* W = dir ? WihB : WihF;
    const float* wp = W + (size_t)g * WIH_STRIDE;
    float s = 0.f;
    for (int k = DW + lane; k < WIH_STRIDE; k += 32) s += wp[k];
    #pragma unroll
    for (int off = 16; off; off >>= 1) s += __shfl_xor_sync(0xffffffffu, s, off);
    if (lane == 0) {
        g_wsum[row] = s;
        g_bias[row] = dir ? (bihB[g] + bhhB[g]) : (bihF[g] + bhhF[g]);
    }
    if (blockIdx.x == 0 && tid == 0) { g_loss_sum = 0.f; g_loss_cnt = 0.f; }
}

// ---------------- kernel 3: input projection GEMM ----------------
// C[m,n] = word[m,:768] @ Wih_dir[g,:768]^T  + v[m]*wsum[n] + bias[n]
// M=8192 (m = b*256+s), N=2048 (n = dir*1024+g), K=768.
// 128x128x8 tile, 256 threads, 8x8 per thread.
__global__ void __launch_bounds__(256) gemm_pre_kernel(const float* __restrict__ A,
                                                       const float* __restrict__ WihF,
                                                       const float* __restrict__ WihB) {
    __shared__ float As[8][128];
    __shared__ float Bs[8][128];
    int tid = threadIdx.x;
    int rowBase = blockIdx.y * 128;
    int colBase = blockIdx.x * 128;
    int lm = tid >> 1;             // 0..127
    int lk = (tid & 1) << 2;       // 0 or 4
    int tx = tid & 15, ty = tid >> 4;

    float acc[8][8];
    #pragma unroll
    for (int i = 0; i < 8; ++i)
        #pragma unroll
        for (int j = 0; j < 8; ++j) acc[i][j] = 0.f;

    const float* Aload = A + (size_t)(rowBase + lm) * DW + lk;
    int ncol = colBase + lm;
    const float* W = (ncol >= G4) ? WihB : WihF;
    const float* Bload = W + (size_t)(ncol & 1023) * WIH_STRIDE + lk;

    for (int kt = 0; kt < DW; kt += 8) {
        float4 a4 = *(const float4*)(Aload + kt);
        float4 b4 = *(const float4*)(Bload + kt);
        As[lk+0][lm] = a4.x; As[lk+1][lm] = a4.y; As[lk+2][lm] = a4.z; As[lk+3][lm] = a4.w;
        Bs[lk+0][lm] = b4.x; Bs[lk+1][lm] = b4.y; Bs[lk+2][lm] = b4.z; Bs[lk+3][lm] = b4.w;
        __syncthreads();
        #pragma unroll
        for (int k = 0; k < 8; ++k) {
            float af[8], bf[8];
            #pragma unroll
            for (int i = 0; i < 8; ++i) af[i] = As[k][ty*8 + i];
            #pragma unroll
            for (int j = 0; j < 8; ++j) bf[j] = Bs[k][tx*8 + j];
            #pragma unroll
            for (int i = 0; i < 8; ++i)
                #pragma unroll
                for (int j = 0; j < 8; ++j) acc[i][j] += af[i] * bf[j];
        }
        __syncthreads();
    }

    #pragma unroll
    for (int i = 0; i < 8; ++i) {
        int m  = rowBase + ty*8 + i;
        int bb = m >> 8;
        int ss = m & 255;
        float vm = g_v[m];
        #pragma unroll
        for (int j = 0; j < 8; ++j) {
            int n   = colBase + tx*8 + j;
            int dir = n >> 10;
            int g   = n & 1023;
            g_pre[(((size_t)dir*SS + ss)*G4 + g)*BB + bb] = acc[i][j] + vm * g_wsum[n] + g_bias[n];
        }
    }
}

// ---------------- kernel 4: bidirectional LSTM recurrence ----------------
// 128 persistent CTAs: dir = bid>>6, slice = bid&63 owns j in [slice*4, slice*4+4).
// thread (jl, b): computes gates i,f,g,o for (b, j0+jl). Whh slice in smem (16KB),
// full h (32KB) reloaded from global each step; custom grid barrier per step.
__global__ void __launch_bounds__(128) lstm_kernel(const float* __restrict__ WhhF,
                                                   const float* __restrict__ WhhB) {
    int dir   = blockIdx.x >> 6;
    int slice = blockIdx.x & 63;
    int j0    = slice << 2;
    int tid   = threadIdx.x;
    int b     = tid & 31;
    int jl    = tid >> 5;
    int j     = j0 + jl;

    __shared__ float ws[4][4][HH];   // [gate][jl][k]  16KB
    __shared__ float hs[HH * BB];    // [k][b]         32KB

    const float* Whh = dir ? WhhB : WhhF;
    for (int i = tid; i < 16 * HH; i += 128) {
        int r = i >> 8, k = i & 255;
        int gate = r >> 2, jj = r & 3;
        ws[gate][jj][k] = Whh[(size_t)((gate << 8) + j0 + jj) * HH + k];
    }

    float c = 0.f;
    const float* preBase = g_pre + (size_t)dir * SS * G4 * BB;
    float* hbD = g_hbuf + (size_t)dir * 2 * HH * BB;

    for (int ts = 0; ts < SS; ++ts) {
        int t = dir ? (SS - 1 - ts) : ts;
        if (ts > 0) {
            const float* hg = hbD + (ts & 1) * HH * BB;
            for (int i = tid * 4; i < HH * BB; i += 128 * 4)
                *(float4*)&hs[i] = *(const float4*)&hg[i];
        }
        __syncthreads();

        const float* pr = preBase + (size_t)t * G4 * BB;
        float ai = pr[(0*HH + j)*BB + b];
        float af = pr[(1*HH + j)*BB + b];
        float ag = pr[(2*HH + j)*BB + b];
        float ao = pr[(3*HH + j)*BB + b];

        if (ts > 0) {
            #pragma unroll 8
            for (int k = 0; k < HH; ++k) {
                float hv = hs[k*32 + b];
                ai += ws[0][jl][k] * hv;
                af += ws[1][jl][k] * hv;
                ag += ws[2][jl][k] * hv;
                ao += ws[3][jl][k] * hv;
            }
        }

        float iv = sigmoidf_(ai);
        float fv = sigmoidf_(af);
        float gv = tanhf(ag);
        float ov = sigmoidf_(ao);
        c = fv * c + iv * gv;
        float h = ov * tanhf(c);

        hbD[((ts + 1) & 1) * HH * BB + j * BB + b] = h;
        g_hs[(((size_t)dir * SS + t) * BB + b) * HH + j] = h;

        gridbar(128);
    }
}

// ---------------- kernel 5: emissions + NLL partial sums ----------------
__global__ void __launch_bounds__(256) emis_kernel(const int* __restrict__ labels,
                                                   const float* __restrict__ Wtag,
                                                   const float* __restrict__ btag) {
    __shared__ float wt[NTAG * 512];
    __shared__ float bt[NTAG];
    int tid = threadIdx.x;
    for (int i = tid; i < NTAG * 512; i += 256) wt[i] = Wtag[i];
    if (tid < NTAG) bt[tid] = btag[tid];
    __syncthreads();

    int idx = blockIdx.x * 256 + tid;      // 0..8191
    int b = idx >> 8, t = idx & 255;

    float acc[NTAG];
    #pragma unroll
    for (int q = 0; q < NTAG; ++q) acc[q] = bt[q];

    #pragma unroll
    for (int part = 0; part < 2; ++part) {
        const float* hp = g_hs + (((size_t)part * SS + t) * BB + b) * HH;
        for (int k4 = 0; k4 < HH; k4 += 4) {
            float4 h4 = *(const float4*)&hp[k4];
            #pragma unroll
            for (int q = 0; q < NTAG; ++q) {
                const float* w = &wt[q * 512 + part * HH + k4];
                acc[q] += h4.x * w[0] + h4.y * w[1] + h4.z * w[2] + h4.w * w[3];
            }
        }
    }

    int lab = labels[idx];
    float nll = 0.f, cnt = 0.f;
    if (lab != -100) {
        int lc = lab < 0 ? 0 : lab;
        float m = acc[0];
        #pragma unroll
        for (int q = 1; q < NTAG; ++q) m = fmaxf(m, acc[q]);
        float s = 0.f;
        #pragma unroll
        for (int q = 0; q < NTAG; ++q) s += __expf(acc[q] - m);
        nll = m + logf(s) - acc[lc];
        cnt = 1.f;
    }
    #pragma unroll
    for (int off = 16; off; off >>= 1) {
        nll += __shfl_xor_sync(0xffffffffu, nll, off);
        cnt += __shfl_xor_sync(0xffffffffu, cnt, off);
    }
    if ((tid & 31) == 0) {
        atomicAdd(&g_loss_sum, nll);
        atomicAdd(&g_loss_cnt, cnt);
    }
}

// ---------------- kernel 6: finalize ----------------
__global__ void finalize_kernel(float* out) {
    out[0] = g_loss_sum / fmaxf(g_loss_cnt, 1.f);
}

// ---------------- launch ----------------
extern "C" void kernel_launch(void* const* d_in, const int* in_sizes, int n_in,
                              void* d_out, int out_size) {
    const float* word_embs = (const float*)d_in[0];
    const float* char_embs = (const float*)d_in[1];
    const int*   spans     = (const int*)  d_in[2];
    const int*   labels    = (const int*)  d_in[3];
    const float* WihF      = (const float*)d_in[4];
    const float* WhhF      = (const float*)d_in[5];
    const float* bihF      = (const float*)d_in[6];
    const float* bhhF      = (const float*)d_in[7];
    const float* WihB      = (const float*)d_in[8];
    const float* WhhB      = (const float*)d_in[9];
    const float* bihB      = (const float*)d_in[10];
    const float* bhhB      = (const float*)d_in[11];
    const float* Wtag      = (const float*)d_in[12];
    const float* btag      = (const float*)d_in[13];
    float* out = (float*)d_out;

    prep_v_kernel<<<1024, 256>>>(char_embs, spans);
    prep_w_kernel<<<256, 256>>>(WihF, WihB, bihF, bhhF, bihB, bhhB);
    gemm_pre_kernel<<<dim3(16, 64), 256>>>(word_embs, WihF, WihB);
    lstm_kernel<<<128, 128>>>(WhhF, WhhB);
    emis_kernel<<<32, 256>>>(labels, Wtag, btag);
    finalize_kernel<<<1, 1>>>(out);
}

// round 4
// speedup vs baseline: 1.2180x; 1.2180x over previous
#include <cuda_runtime.h>
#include <math.h>

#define BB   32
#define SS   256
#define CC   1024
#define DW   768
#define HH   256
#define G4   1024          // 4*H
#define NTAG 9
#define WIH_STRIDE 2816

// ---------------- scratch (static device globals; no allocations) ----------------
__device__ __align__(16) float g_v[BB*SS];                 // [b][s] broadcast scalar
__device__ __align__(16) float g_wsum[2*G4];               // [dir][gate] rowsum of Wih[:,768:]
__device__ __align__(16) float g_bias[2*G4];               // bih+bhh
__device__ __align__(16) float g_pre[(size_t)2*SS*BB*G4];  // [dir][t][b][g4]  (64 MB)
__device__ __align__(16) float g_hbuf[2*2*HH*BB];          // [dir][parity][j][b]
__device__ __align__(16) float g_hs[(size_t)2*SS*BB*HH];   // [dir][t][b][j]  (16 MB)
__device__ float g_loss_sum;
__device__ float g_loss_cnt;
__device__ unsigned g_flag[2][64];                         // per-direction per-CTA step flags

// ---------------- helpers ----------------
__device__ __forceinline__ float sigmoidf_(float x) { return 1.f / (1.f + __expf(-x)); }

__device__ __forceinline__ unsigned ldacq(const unsigned* p) {
    unsigned v;
    asm volatile("ld.acquire.gpu.u32 %0, [%1];" : "=r"(v) : "l"(p));
    return v;
}
__device__ __forceinline__ void strel(unsigned* p, unsigned v) {
    asm volatile("st.release.gpu.u32 [%0], %1;" :: "l"(p), "r"(v));
}
__device__ __forceinline__ unsigned f2tf(float x) {
    unsigned r;
    asm("cvt.rna.tf32.f32 %0, %1;" : "=r"(r) : "f"(x));
    return r;
}
__device__ __forceinline__ float4 tf4(float4 v) {
    float4 o;
    o.x = __uint_as_float(f2tf(v.x));
    o.y = __uint_as_float(f2tf(v.y));
    o.z = __uint_as_float(f2tf(v.z));
    o.w = __uint_as_float(f2tf(v.w));
    return o;
}
__device__ __forceinline__ void mma_tf32(float* c, const unsigned* a, const unsigned* b) {
    asm volatile(
        "mma.sync.aligned.m16n8k8.row.col.f32.tf32.tf32.f32 "
        "{%0,%1,%2,%3}, {%4,%5,%6,%7}, {%8,%9}, {%0,%1,%2,%3};"
        : "+f"(c[0]), "+f"(c[1]), "+f"(c[2]), "+f"(c[3])
        : "r"(a[0]), "r"(a[1]), "r"(a[2]), "r"(a[3]), "r"(b[0]), "r"(b[1]));
}

// ---------------- kernel 1: segment-mean scalar v[b,s] ----------------
__global__ void __launch_bounds__(256) prep_v_kernel(const float* __restrict__ char_embs,
                                                     const int*   __restrict__ spans) {
    int tid  = threadIdx.x;
    int lane = tid & 31;
    int token = blockIdx.x * 8 + (tid >> 5);
    int st = spans[token * 2 + 0];
    int en = spans[token * 2 + 1];
    float s = 0.f;
    if (st >= 0) {
        int b = token >> 8;
        for (int c = st; c <= en; ++c) {
            const float* p = char_embs + ((size_t)(b * CC + c)) * DW;
            float acc = 0.f;
            for (int d = lane; d < DW; d += 32) acc += p[d];
            s += acc;
        }
        #pragma unroll
        for (int off = 16; off; off >>= 1) s += __shfl_xor_sync(0xffffffffu, s, off);
        s /= (768.f * (float)(en - st + 1));
    }
    if (lane == 0) g_v[token] = (st >= 0) ? s : 0.f;
}

// ---------------- kernel 2: wsum + bias + zero accumulators/flags ----------------
__global__ void __launch_bounds__(256) prep_w_kernel(
        const float* __restrict__ WihF, const float* __restrict__ WihB,
        const float* __restrict__ bihF, const float* __restrict__ bhhF,
        const float* __restrict__ bihB, const float* __restrict__ bhhB) {
    int tid  = threadIdx.x;
    int lane = tid & 31;
    int row  = blockIdx.x * 8 + (tid >> 5);     // 0..2047
    int dir  = row >> 10;
    int g    = row & 1023;
    const float* W = dir ? WihB : WihF;
    const float* wp = W + (size_t)g * WIH_STRIDE;
    float s = 0.f;
    for (int k = DW + lane; k < WIH_STRIDE; k += 32) s += wp[k];
    #pragma unroll
    for (int off = 16; off; off >>= 1) s += __shfl_xor_sync(0xffffffffu, s, off);
    if (lane == 0) {
        g_wsum[row] = s;
        g_bias[row] = dir ? (bihB[g] + bhhB[g]) : (bihF[g] + bhhF[g]);
    }
    if (blockIdx.x == 0) {
        if (tid == 0) { g_loss_sum = 0.f; g_loss_cnt = 0.f; }
        if (tid < 128) ((unsigned*)g_flag)[tid] = 0u;
    }
}

// ---------------- kernel 3: input projection GEMM (tf32 tensor cores) ----------------
// C[m,n] = word[m,:768] @ Wih_dir[g,:768]^T + v[m]*wsum[n] + bias[n]
// M=8192 (m=b*256+s), N=2048 (n=dir*1024+g), K=768.
// 128x128x32 CTA tile, 8 warps (2x4), each warp 64x32 via 4x4 m16n8k8 mma.
// Output layout g_pre[dir][t][b][g]: lanes vary g -> float2 stores fill sectors.
__global__ void __launch_bounds__(256, 1) gemm_pre_kernel(const float* __restrict__ A,
                                                          const float* __restrict__ WihF,
                                                          const float* __restrict__ WihB) {
    __shared__ float As[128 * 36];
    __shared__ float Bs[128 * 36];
    int tid  = threadIdx.x;
    int lane = tid & 31;
    int warp = tid >> 5;
    int wm = warp >> 2;            // 0..1
    int wn = warp & 3;             // 0..3
    int rowBase = blockIdx.y * 128;
    int nBase   = blockIdx.x * 128;

    int lrow = tid >> 3;           // 0..31
    int lq   = tid & 7;            // 0..7 -> col lq*4

    const float* aPtr[4];
    const float* bPtr[4];
    #pragma unroll
    for (int p = 0; p < 4; ++p) {
        int r = lrow + p * 32;
        aPtr[p] = A + (size_t)(rowBase + r) * DW + lq * 4;
        int n = nBase + r;
        const float* W = (n >= G4) ? WihB : WihF;
        bPtr[p] = W + (size_t)(n & 1023) * WIH_STRIDE + lq * 4;
    }

    float acc[4][4][4];
    #pragma unroll
    for (int mt = 0; mt < 4; ++mt)
        #pragma unroll
        for (int nt = 0; nt < 4; ++nt)
            #pragma unroll
            for (int q = 0; q < 4; ++q) acc[mt][nt][q] = 0.f;

    float4 ra[4], rb[4];
    #pragma unroll
    for (int p = 0; p < 4; ++p) {
        ra[p] = *(const float4*)aPtr[p];
        rb[p] = *(const float4*)bPtr[p];
    }

    for (int kt = 0; kt < DW; kt += 32) {
        if (kt) __syncthreads();
        #pragma unroll
        for (int p = 0; p < 4; ++p) {
            int r = lrow + p * 32;
            *(float4*)&As[r * 36 + lq * 4] = tf4(ra[p]);
            *(float4*)&Bs[r * 36 + lq * 4] = tf4(rb[p]);
        }
        __syncthreads();
        if (kt + 32 < DW) {
            #pragma unroll
            for (int p = 0; p < 4; ++p) {
                ra[p] = *(const float4*)(aPtr[p] + kt + 32);
                rb[p] = *(const float4*)(bPtr[p] + kt + 32);
            }
        }
        int q  = lane & 3;
        int gp = lane >> 2;
        #pragma unroll
        for (int kc = 0; kc < 32; kc += 8) {
            unsigned afr[4][4], bfr[4][2];
            #pragma unroll
            for (int mt = 0; mt < 4; ++mt) {
                int r = wm * 64 + mt * 16 + gp;
                afr[mt][0] = __float_as_uint(As[r * 36 + kc + q]);
                afr[mt][1] = __float_as_uint(As[(r + 8) * 36 + kc + q]);
                afr[mt][2] = __float_as_uint(As[r * 36 + kc + q + 4]);
                afr[mt][3] = __float_as_uint(As[(r + 8) * 36 + kc + q + 4]);
            }
            #pragma unroll
            for (int nt = 0; nt < 4; ++nt) {
                int c = wn * 32 + nt * 8 + gp;
                bfr[nt][0] = __float_as_uint(Bs[c * 36 + kc + q]);
                bfr[nt][1] = __float_as_uint(Bs[c * 36 + kc + q + 4]);
            }
            #pragma unroll
            for (int mt = 0; mt < 4; ++mt)
                #pragma unroll
                for (int nt = 0; nt < 4; ++nt)
                    mma_tf32(acc[mt][nt], afr[mt], bfr[nt]);
        }
    }

    // epilogue: b fixed per CTA (128-row M tile within one batch)
    int b = rowBase >> 8;
    #pragma unroll
    for (int mt = 0; mt < 4; ++mt) {
        int r0 = wm * 64 + mt * 16 + (lane >> 2);
        int m0 = rowBase + r0;
        float v0 = g_v[m0];
        float v1 = g_v[m0 + 8];
        int ss0 = m0 & 255;
        #pragma unroll
        for (int nt = 0; nt < 4; ++nt) {
            int n0  = nBase + wn * 32 + nt * 8 + 2 * (lane & 3);
            int dir = n0 >> 10;
            int g   = n0 & 1023;
            float2 w2  = *(const float2*)&g_wsum[n0];
            float2 bi2 = *(const float2*)&g_bias[n0];
            size_t base0 = (((size_t)dir * SS + ss0) * BB + b) * G4 + g;
            float2 o0 = make_float2(acc[mt][nt][0] + v0 * w2.x + bi2.x,
                                    acc[mt][nt][1] + v0 * w2.y + bi2.y);
            *(float2*)&g_pre[base0] = o0;
            size_t base1 = (((size_t)dir * SS + (ss0 + 8)) * BB + b) * G4 + g;
            float2 o1 = make_float2(acc[mt][nt][2] + v1 * w2.x + bi2.x,
                                    acc[mt][nt][3] + v1 * w2.y + bi2.y);
            *(float2*)&g_pre[base1] = o1;
        }
    }
}

// ---------------- kernel 4: bidirectional LSTM recurrence ----------------
// 128 persistent CTAs: dir = bid>>6, slice = bid&63 owns j in [slice*4, slice*4+4).
// Distributed per-direction flag barrier (release/acquire), Whh gates packed float4,
// pre staged through smem, h written via smem transpose.
__global__ void __launch_bounds__(128) lstm_kernel(const float* __restrict__ WhhF,
                                                   const float* __restrict__ WhhB) {
    extern __shared__ float sm[];
    float4* ws4  = (float4*)sm;          // [jl][k] : 1024 float4 = 16 KB
    float*  hsm  = sm + 4096;            // [k][b]  : 8192 floats = 32 KB
    float*  pre_s = sm + 12288;          // [b][20] : 640 floats
    float*  hout  = sm + 12928;          // [jl][b] : 128 floats

    int dir   = blockIdx.x >> 6;
    int slice = blockIdx.x & 63;
    int j0    = slice << 2;
    int tid   = threadIdx.x;
    int b     = tid & 31;
    int jl    = tid >> 5;
    int j     = j0 + jl;

    const float* Whh = dir ? WhhB : WhhF;
    for (int i = tid; i < 4 * HH; i += 128) {
        int jj = i >> 8, k = i & 255;
        float4 w;
        w.x = Whh[(size_t)((0 << 8) + j0 + jj) * HH + k];
        w.y = Whh[(size_t)((1 << 8) + j0 + jj) * HH + k];
        w.z = Whh[(size_t)((2 << 8) + j0 + jj) * HH + k];
        w.w = Whh[(size_t)((3 << 8) + j0 + jj) * HH + k];
        ws4[jj * 256 + k] = w;
    }

    float c = 0.f;
    const float* preBase = g_pre + (size_t)dir * SS * BB * G4;
    float* hbD = g_hbuf + (size_t)dir * 2 * HH * BB;
    int bq = tid >> 2, ch = tid & 3;

    for (int ts = 0; ts < SS; ++ts) {
        int t = dir ? (SS - 1 - ts) : ts;

        // (a) stage pre-activations: float4 per (b, gate) chunk
        float4 p4 = *(const float4*)&preBase[(((size_t)t) * BB + bq) * G4 + ch * 256 + j0];
        *(float4*)&pre_s[bq * 20 + ch * 4] = p4;

        // (b) wait: all 64 CTAs of this direction finished step ts-1
        if (ts > 0 && tid < 64) {
            const unsigned* f = &g_flag[dir][tid];
            while (ldacq(f) < (unsigned)ts) { }
        }
        __syncthreads();   // (c)

        // (d) copy h(ts-1) to smem; read own pre
        if (ts > 0) {
            const float* hg = hbD + (ts & 1) * (HH * BB);
            for (int i = tid * 4; i < HH * BB; i += 128 * 4)
                *(float4*)&hsm[i] = *(const float4*)&hg[i];
        }
        float ai = pre_s[b * 20 + 0 + jl];
        float af = pre_s[b * 20 + 4 + jl];
        float ag = pre_s[b * 20 + 8 + jl];
        float ao = pre_s[b * 20 + 12 + jl];
        __syncthreads();   // (e)

        // (f) recurrence matvec
        if (ts > 0) {
            #pragma unroll 8
            for (int k = 0; k < HH; ++k) {
                float hv = hsm[(k << 5) + b];
                float4 w = ws4[(jl << 8) + k];
                ai = fmaf(w.x, hv, ai);
                af = fmaf(w.y, hv, af);
                ag = fmaf(w.z, hv, ag);
                ao = fmaf(w.w, hv, ao);
            }
        }

        float iv = sigmoidf_(ai);
        float fv = sigmoidf_(af);
        float gv = tanhf(ag);
        float ov = sigmoidf_(ao);
        c = fv * c + iv * gv;
        float h = ov * tanhf(c);

        // (g) publish h
        hbD[((ts + 1) & 1) * (HH * BB) + (j << 5) + b] = h;
        hout[(jl << 5) + b] = h;
        __syncthreads();   // (h)

        if (tid == 0) strel(&g_flag[dir][slice], (unsigned)(ts + 1));

        // (i) coalesced-ish g_hs write: float4 per (t, b)
        if (tid < 32) {
            float4 h4;
            h4.x = hout[tid];
            h4.y = hout[32 + tid];
            h4.z = hout[64 + tid];
            h4.w = hout[96 + tid];
            *(float4*)&g_hs[(((size_t)dir * SS + t) * BB + tid) * HH + j0] = h4;
        }
    }
}

// ---------------- kernel 5: emissions + NLL partial sums ----------------
__global__ void __launch_bounds__(256) emis_kernel(const int* __restrict__ labels,
                                                   const float* __restrict__ Wtag,
                                                   const float* __restrict__ btag) {
    __shared__ float wt[NTAG * 512];
    __shared__ float bt[NTAG];
    int tid = threadIdx.x;
    for (int i = tid; i < NTAG * 512; i += 256) wt[i] = Wtag[i];
    if (tid < NTAG) bt[tid] = btag[tid];
    __syncthreads();

    int idx = blockIdx.x * 256 + tid;      // 0..8191
    int b = idx >> 8, t = idx & 255;

    float acc[NTAG];
    #pragma unroll
    for (int q = 0; q < NTAG; ++q) acc[q] = bt[q];

    #pragma unroll
    for (int part = 0; part < 2; ++part) {
        const float* hp = g_hs + (((size_t)part * SS + t) * BB + b) * HH;
        for (int k4 = 0; k4 < HH; k4 += 4) {
            float4 h4 = *(const float4*)&hp[k4];
            #pragma unroll
            for (int q = 0; q < NTAG; ++q) {
                const float* w = &wt[q * 512 + part * HH + k4];
                acc[q] += h4.x * w[0] + h4.y * w[1] + h4.z * w[2] + h4.w * w[3];
            }
        }
    }

    int lab = labels[idx];
    float nll = 0.f, cnt = 0.f;
    if (lab != -100) {
        int lc = lab < 0 ? 0 : lab;
        float m = acc[0];
        #pragma unroll
        for (int q = 1; q < NTAG; ++q) m = fmaxf(m, acc[q]);
        float s = 0.f;
        #pragma unroll
        for (int q = 0; q < NTAG; ++q) s += __expf(acc[q] - m);
        nll = m + logf(s) - acc[lc];
        cnt = 1.f;
    }
    #pragma unroll
    for (int off = 16; off; off >>= 1) {
        nll += __shfl_xor_sync(0xffffffffu, nll, off);
        cnt += __shfl_xor_sync(0xffffffffu, cnt, off);
    }
    if ((tid & 31) == 0) {
        atomicAdd(&g_loss_sum, nll);
        atomicAdd(&g_loss_cnt, cnt);
    }
}

// ---------------- kernel 6: finalize ----------------
__global__ void finalize_kernel(float* out) {
    out[0] = g_loss_sum / fmaxf(g_loss_cnt, 1.f);
}

// ---------------- launch ----------------
extern "C" void kernel_launch(void* const* d_in, const int* in_sizes, int n_in,
                              void* d_out, int out_size) {
    const float* word_embs = (const float*)d_in[0];
    const float* char_embs = (const float*)d_in[1];
    const int*   spans     = (const int*)  d_in[2];
    const int*   labels    = (const int*)  d_in[3];
    const float* WihF      = (const float*)d_in[4];
    const float* WhhF      = (const float*)d_in[5];
    const float* bihF      = (const float*)d_in[6];
    const float* bhhF      = (const float*)d_in[7];
    const float* WihB      = (const float*)d_in[8];
    const float* WhhB      = (const float*)d_in[9];
    const float* bihB      = (const float*)d_in[10];
    const float* bhhB      = (const float*)d_in[11];
    const float* Wtag      = (const float*)d_in[12];
    const float* btag      = (const float*)d_in[13];
    float* out = (float*)d_out;

    cudaFuncSetAttribute(lstm_kernel, cudaFuncAttributeMaxDynamicSharedMemorySize, 52224);

    prep_v_kernel<<<1024, 256>>>(char_embs, spans);
    prep_w_kernel<<<256, 256>>>(WihF, WihB, bihF, bhhF, bihB, bhhB);
    gemm_pre_kernel<<<dim3(16, 64), 256>>>(word_embs, WihF, WihB);
    lstm_kernel<<<128, 128, 52224>>>(WhhF, WhhB);
    emis_kernel<<<32, 256>>>(labels, Wtag, btag);
    finalize_kernel<<<1, 1>>>(out);
}